// round 3
// baseline (speedup 1.0000x reference)
#include <cuda_runtime.h>
#include <cuda_bf16.h>

#define NN 20000
#define NE 100000

__device__ float g_ebn[NE * 10];
__device__ float g_h1[NE * 16];
__device__ float g_h2[NE * 32];
__device__ float g_xbn[NN * 16];
__device__ float g_x1[NN * 32];
__device__ float g_x2[NN * 64];
__device__ float g_m1[NE * 64];            // edge-MLP layer1 activations
__device__ float g_wT1[2 * 16 * 32 * 9];   // conv1 weights (stride-9 pad, scalar)
__device__ float g_wT2[8 * 32 * 64 * 4];   // conv2 weights [ic8][j][o][il4] (float4)
__device__ float g_emean[10], g_ers[10];
__device__ float g_xmean[16], g_xrs[16];

__device__ __forceinline__ float lrelu(float v) { return v > 0.f ? v : 0.1f * v; }

// ---------------- BatchNorm statistics (biased var, eps=1e-5) ----------------
__device__ void bn_stats_impl(const float* __restrict__ v, int rows, int cols,
                              float* mean_out, float* rs_out) {
    int c = blockIdx.x;
    int tid = threadIdx.x;
    double s = 0.0, ss = 0.0;
    for (int r = tid; r < rows; r += blockDim.x) {
        float f = v[(size_t)r * cols + c];
        s += (double)f;
        ss += (double)f * (double)f;
    }
    __shared__ double sh[256];
    sh[tid] = s; __syncthreads();
    for (int off = 128; off > 0; off >>= 1) { if (tid < off) sh[tid] += sh[tid + off]; __syncthreads(); }
    double stot = sh[0]; __syncthreads();
    sh[tid] = ss; __syncthreads();
    for (int off = 128; off > 0; off >>= 1) { if (tid < off) sh[tid] += sh[tid + off]; __syncthreads(); }
    if (tid == 0) {
        double m = stot / rows;
        double var = sh[0] / rows - m * m;
        mean_out[c] = (float)m;
        rs_out[c] = (float)(1.0 / sqrt(var + 1e-5));
    }
}

__global__ void bn_stats_edge(const float* __restrict__ e) { bn_stats_impl(e, NE, 10, g_emean, g_ers); }
__global__ void bn_stats_node(const float* __restrict__ x) { bn_stats_impl(x, NN, 16, g_xmean, g_xrs); }

// ---------------- weight transposes ------------------------------------------
__global__ void prep_w1(const float* __restrict__ w) {  // nn1_w2 [16,512]
    int idx = blockIdx.x * 256 + threadIdx.x;           // 8192 items
    if (idx >= 8192) return;
    int il = idx & 7, o = (idx >> 3) & 31, j = (idx >> 8) & 15, ic = (idx >> 12) & 1;
    g_wT1[((ic * 16 + j) * 32 + o) * 9 + il] = w[j * 512 + (ic * 8 + il) * 32 + o];
}
__global__ void prep_w2(const float* __restrict__ w) {  // nn2_w2 [32,2048]
    int idx = blockIdx.x * 256 + threadIdx.x;           // 65536 items
    int il = idx & 3, o = (idx >> 2) & 63, j = (idx >> 8) & 31, ic = (idx >> 13) & 7;
    g_wT2[((ic * 32 + j) * 64 + o) * 4 + il] = w[j * 2048 + (ic * 4 + il) * 64 + o];
}

// ---------------- K1: edge BN + h1 + h2 --------------------------------------
__global__ void k1_edge(const float* __restrict__ e,
                        const float* __restrict__ eg, const float* __restrict__ eb,
                        const float* __restrict__ w1, const float* __restrict__ b1,
                        const float* __restrict__ w2, const float* __restrict__ b2) {
    __shared__ float sw1[160], sw2[320], sb1[16], sb2[32], sg[10], sb[10], sm[10], srs[10];
    int tid = threadIdx.x;
    for (int i = tid; i < 160; i += 256) sw1[i] = w1[i];
    for (int i = tid; i < 320; i += 256) sw2[i] = w2[i];
    if (tid < 16) sb1[tid] = b1[tid];
    if (tid < 32) sb2[tid] = b2[tid];
    if (tid < 10) { sg[tid] = eg[tid]; sb[tid] = eb[tid]; sm[tid] = g_emean[tid]; srs[tid] = g_ers[tid]; }
    __syncthreads();
    int eid = blockIdx.x * 256 + tid;
    if (eid >= NE) return;
    float ev[10];
#pragma unroll
    for (int c = 0; c < 10; c++) {
        float f = (e[eid * 10 + c] - sm[c]) * srs[c] * sg[c] + sb[c];
        ev[c] = f;
        g_ebn[eid * 10 + c] = f;
    }
#pragma unroll
    for (int o = 0; o < 16; o++) {
        float t = sb1[o];
#pragma unroll
        for (int c = 0; c < 10; c++) t += ev[c] * sw1[c * 16 + o];
        g_h1[eid * 16 + o] = lrelu(t);
    }
#pragma unroll
    for (int o = 0; o < 32; o++) {
        float t = sb2[o];
#pragma unroll
        for (int c = 0; c < 10; c++) t += ev[c] * sw2[c * 32 + o];
        g_h2[eid * 32 + o] = lrelu(t);
    }
}

// ---------------- K2: node BN + x1 = xbn @ l1_root + l1_bias -----------------
__global__ void k2_node(const float* __restrict__ x,
                        const float* __restrict__ ng, const float* __restrict__ nb,
                        const float* __restrict__ root, const float* __restrict__ bias) {
    __shared__ float sroot[512], sbias[32], sg[16], sb[16], sm[16], srs[16];
    int tid = threadIdx.x;
    for (int i = tid; i < 512; i += 256) sroot[i] = root[i];
    if (tid < 32) sbias[tid] = bias[tid];
    if (tid < 16) { sg[tid] = ng[tid]; sb[tid] = nb[tid]; sm[tid] = g_xmean[tid]; srs[tid] = g_xrs[tid]; }
    __syncthreads();
    int nid = blockIdx.x * 256 + tid;
    if (nid >= NN) return;
    float xv[16];
#pragma unroll
    for (int i = 0; i < 16; i++) {
        float f = (x[nid * 16 + i] - sm[i]) * srs[i] * sg[i] + sb[i];
        xv[i] = f;
        g_xbn[nid * 16 + i] = f;
    }
#pragma unroll
    for (int o = 0; o < 32; o++) {
        float t = sbias[o];
#pragma unroll
        for (int i = 0; i < 16; i++) t += xv[i] * sroot[i * 32 + o];
        g_x1[nid * 32 + o] = t;
    }
}

// ---------------- K3: NNConv1 message + scatter ------------------------------
__global__ __launch_bounds__(256) void k3_conv1(const int* __restrict__ ei,
                                                const float* __restrict__ b2) {
    __shared__ __align__(16) float swT[9216];     // 2*16*32*9
    __shared__ __align__(16) float h_sh[16 * 68];
    __shared__ __align__(16) float x_sh[64 * 16];
    __shared__ int dst_sh[64];
    int tid = threadIdx.x;
    int e0 = blockIdx.x * 64;
    for (int i = tid; i < 9216; i += 256) swT[i] = g_wT1[i];
    if (tid < 64) {
        int ge = e0 + tid;
        dst_sh[tid] = (ge < NE) ? ei[NE + ge] : 0;
    }
    for (int i = tid; i < 1024; i += 256) {
        int el = i >> 4, j = i & 15;
        int ge = e0 + el;
        h_sh[j * 68 + el] = (ge < NE) ? g_h1[ge * 16 + j] : 0.f;
    }
    for (int i = tid; i < 1024; i += 256) {
        int el = i >> 4, ii = i & 15;
        int ge = e0 + el;
        x_sh[el * 16 + ii] = (ge < NE) ? g_xbn[ei[ge] * 16 + ii] : 0.f;
    }
    __syncthreads();

    int o = tid & 31;
    int w = tid >> 5;
    float acc[8];
#pragma unroll
    for (int eL = 0; eL < 8; eL++) acc[eL] = 0.f;

#pragma unroll
    for (int ic = 0; ic < 2; ic++) {
        float bl[8];
#pragma unroll
        for (int il = 0; il < 8; il++) bl[il] = b2[(ic * 8 + il) * 32 + o];
        float t[8][8];
#pragma unroll
        for (int eL = 0; eL < 8; eL++)
#pragma unroll
            for (int il = 0; il < 8; il++) t[eL][il] = bl[il];

#pragma unroll 4
        for (int j = 0; j < 16; j++) {
            float4 ha = *(const float4*)&h_sh[j * 68 + w * 8];
            float4 hb = *(const float4*)&h_sh[j * 68 + w * 8 + 4];
            float hv[8] = {ha.x, ha.y, ha.z, ha.w, hb.x, hb.y, hb.z, hb.w};
            const float* wp = &swT[((ic * 16 + j) * 32 + o) * 9];
            float wr[8];
#pragma unroll
            for (int il = 0; il < 8; il++) wr[il] = wp[il];
#pragma unroll
            for (int eL = 0; eL < 8; eL++)
#pragma unroll
                for (int il = 0; il < 8; il++) t[eL][il] += hv[eL] * wr[il];
        }
#pragma unroll
        for (int eL = 0; eL < 8; eL++)
#pragma unroll
            for (int il = 0; il < 8; il++)
                acc[eL] += x_sh[(w * 8 + eL) * 16 + ic * 8 + il] * lrelu(t[eL][il]);
    }
#pragma unroll
    for (int eL = 0; eL < 8; eL++) {
        int ge = e0 + w * 8 + eL;
        if (ge < NE) atomicAdd(&g_x1[dst_sh[w * 8 + eL] * 32 + o], acc[eL]);
    }
}

// ---------------- K4: x2 = x1 @ l2_root + l2_bias ----------------------------
__global__ void k4_node(const float* __restrict__ root, const float* __restrict__ bias) {
    __shared__ float sroot[2048], sbias[64];
    int tid = threadIdx.x;
    for (int i = tid; i < 2048; i += 256) sroot[i] = root[i];
    if (tid < 64) sbias[tid] = bias[tid];
    __syncthreads();
    int idx = blockIdx.x * 256 + tid;
    if (idx >= NN * 64) return;
    int n = idx >> 6, o = idx & 63;
    float t = sbias[o];
#pragma unroll
    for (int i = 0; i < 32; i++) t += g_x1[n * 32 + i] * sroot[i * 64 + o];
    g_x2[idx] = t;
}

// ---------------- K5: NNConv2 message + scatter (dominant) -------------------
// 256 thr, 32 edges/block. o = tid&63, group g = tid>>6 handles 8 edges.
// Weights streamed in 8 chunks of 32KB through static shared; float4 LDS,
// per-lane stride 16B -> conflict-free.
__global__ __launch_bounds__(256) void k5_conv2(const int* __restrict__ ei,
                                                const float* __restrict__ b2) {
    __shared__ __align__(16) float w_sh[8192];   // 32KB chunk: [j][o][il4]
    __shared__ __align__(16) float h_sh[32 * 36];
    __shared__ __align__(16) float x_sh[32 * 32];
    __shared__ int dst_sh[32];
    int tid = threadIdx.x;
    int e0 = blockIdx.x * 32;

    if (tid < 32) dst_sh[tid] = ei[NE + e0 + tid];
    for (int i = tid; i < 1024; i += 256) {
        int el = i >> 5, j = i & 31;
        h_sh[j * 36 + el] = g_h2[(e0 + el) * 32 + j];
    }
    for (int i = tid; i < 1024; i += 256) {
        int el = i >> 5, ii = i & 31;
        x_sh[el * 32 + ii] = g_x1[ei[e0 + el] * 32 + ii];
    }

    int o = tid & 63;
    int g = tid >> 6;
    float acc[8];
#pragma unroll
    for (int eL = 0; eL < 8; eL++) acc[eL] = 0.f;

    for (int ic = 0; ic < 8; ic++) {
        __syncthreads();   // protects h/x initial fill + w_sh reuse
        for (int i = tid; i < 8192; i += 256) w_sh[i] = g_wT2[ic * 8192 + i];
        __syncthreads();

        float bl[4];
#pragma unroll
        for (int il = 0; il < 4; il++) bl[il] = b2[(ic * 4 + il) * 64 + o];
        float t[8][4];
#pragma unroll
        for (int eL = 0; eL < 8; eL++)
#pragma unroll
            for (int il = 0; il < 4; il++) t[eL][il] = bl[il];

#pragma unroll 4
        for (int j = 0; j < 32; j++) {
            float4 ha = *(const float4*)&h_sh[j * 36 + g * 8];
            float4 hb = *(const float4*)&h_sh[j * 36 + g * 8 + 4];
            float hv[8] = {ha.x, ha.y, ha.z, ha.w, hb.x, hb.y, hb.z, hb.w};
            float4 wv = *(const float4*)&w_sh[(j * 64 + o) * 4];
            float wr[4] = {wv.x, wv.y, wv.z, wv.w};
#pragma unroll
            for (int eL = 0; eL < 8; eL++)
#pragma unroll
                for (int il = 0; il < 4; il++) t[eL][il] += hv[eL] * wr[il];
        }
#pragma unroll
        for (int eL = 0; eL < 8; eL++)
#pragma unroll
            for (int il = 0; il < 4; il++)
                acc[eL] += x_sh[(g * 8 + eL) * 32 + ic * 4 + il] * lrelu(t[eL][il]);
    }
#pragma unroll
    for (int eL = 0; eL < 8; eL++)
        atomicAdd(&g_x2[dst_sh[g * 8 + eL] * 64 + o], acc[eL]);
}

// ---------------- K6a: edge MLP layer1 (138 -> 64) ---------------------------
// 256 thr, 16 edges/block. o = tid&63, group g = tid>>6 handles 4 edges.
__global__ __launch_bounds__(256) void k6a_mlp1(const int* __restrict__ ei,
                                                const float* __restrict__ w1,
                                                const float* __restrict__ b1) {
    __shared__ float sw1[138 * 64];               // 34.5KB
    __shared__ float sb1[64];
    __shared__ __align__(16) float in_sh[138 * 20]; // [k][e] pad 20
    int tid = threadIdx.x;
    int e0 = blockIdx.x * 16;

    for (int i = tid; i < 8832; i += 256) sw1[i] = w1[i];
    if (tid < 64) sb1[tid] = b1[tid];
    for (int i = tid; i < 138 * 16; i += 256) {
        int e = i & 15, k = i >> 4;
        float v;
        if (k < 64)       v = g_x2[ei[e0 + e] * 64 + k];
        else if (k < 128) v = g_x2[ei[NE + e0 + e] * 64 + (k - 64)];
        else              v = g_ebn[(e0 + e) * 10 + (k - 128)];
        in_sh[k * 20 + e] = v;
    }
    __syncthreads();

    int o = tid & 63, g = tid >> 6;
    float a[4];
#pragma unroll
    for (int e = 0; e < 4; e++) a[e] = sb1[o];
#pragma unroll 2
    for (int k = 0; k < 138; k++) {
        float wv = sw1[k * 64 + o];
        float4 h = *(const float4*)&in_sh[k * 20 + g * 4];
        a[0] += h.x * wv; a[1] += h.y * wv; a[2] += h.z * wv; a[3] += h.w * wv;
    }
#pragma unroll
    for (int e = 0; e < 4; e++)
        g_m1[(e0 + g * 4 + e) * 64 + o] = lrelu(a[e]);
}

// ---------------- K6b: edge MLP layers 2-5 -----------------------------------
// 256 thr, 32 edges/block.
__global__ __launch_bounds__(256) void k6b_mlp(
    const float* __restrict__ w2, const float* __restrict__ b2,
    const float* __restrict__ w3, const float* __restrict__ b3,
    const float* __restrict__ w4, const float* __restrict__ b4,
    const float* __restrict__ w5, const float* __restrict__ b5,
    float* __restrict__ out) {
    __shared__ float sw2[2048], sw3[512], sw4[128], sw5[16];
    __shared__ float sb2[32], sb3[16], sb4[8], sb5[2];
    __shared__ __align__(16) float h1_sh[64 * 36];  // [k][e] pad 36
    __shared__ __align__(16) float h2_sh[32 * 36];
    int tid = threadIdx.x;
    int e0 = blockIdx.x * 32;

    for (int i = tid; i < 2048; i += 256) sw2[i] = w2[i];
    for (int i = tid; i < 512; i += 256) sw3[i] = w3[i];
    if (tid < 128) sw4[tid] = w4[tid];
    if (tid < 16) sw5[tid] = w5[tid];
    if (tid < 32) sb2[tid] = b2[tid];
    if (tid < 16) sb3[tid] = b3[tid];
    if (tid < 8) sb4[tid] = b4[tid];
    if (tid < 2) sb5[tid] = b5[tid];
    for (int i = tid; i < 2048; i += 256) {
        int e = i & 31, k = i >> 5;
        h1_sh[k * 36 + e] = g_m1[(e0 + e) * 64 + k];
    }
    __syncthreads();

    // layer 2: 64 -> 32, 8 groups x 4 edges
    {
        int o = tid & 31, g = tid >> 5;
        float a[4];
#pragma unroll
        for (int e = 0; e < 4; e++) a[e] = sb2[o];
#pragma unroll 4
        for (int k = 0; k < 64; k++) {
            float wv = sw2[k * 32 + o];
            float4 h = *(const float4*)&h1_sh[k * 36 + g * 4];
            a[0] += h.x * wv; a[1] += h.y * wv; a[2] += h.z * wv; a[3] += h.w * wv;
        }
#pragma unroll
        for (int e = 0; e < 4; e++) h2_sh[o * 36 + g * 4 + e] = lrelu(a[e]);
    }
    __syncthreads();

    // layers 3-5: one thread per edge
    if (tid < 32) {
        int e = tid, ge = e0 + e;
        float h2r[32];
#pragma unroll
        for (int k = 0; k < 32; k++) h2r[k] = h2_sh[k * 36 + e];
        float h3[16];
#pragma unroll
        for (int o = 0; o < 16; o++) {
            float a = sb3[o];
#pragma unroll
            for (int k = 0; k < 32; k++) a += h2r[k] * sw3[k * 16 + o];
            h3[o] = lrelu(a);
        }
        float h4[8];
#pragma unroll
        for (int o = 0; o < 8; o++) {
            float a = sb4[o];
#pragma unroll
            for (int k = 0; k < 16; k++) a += h3[k] * sw4[k * 8 + o];
            h4[o] = lrelu(a);
        }
#pragma unroll
        for (int o = 0; o < 2; o++) {
            float a = sb5[o];
#pragma unroll
            for (int k = 0; k < 8; k++) a += h4[k] * sw5[k * 2 + o];
            out[(size_t)ge * 2 + o] = a;
        }
    }
}

// ---------------- launch -----------------------------------------------------
extern "C" void kernel_launch(void* const* d_in, const int* in_sizes, int n_in,
                              void* d_out, int out_size) {
    const float* x = (const float*)d_in[0];
    const float* e = (const float*)d_in[1];
    const int* ei = (const int*)d_in[2];     // edge_index: int32 (JAX x64 disabled)
    // d_in[3] xbatch unused
    const float* bn_node_g = (const float*)d_in[4];
    const float* bn_node_b = (const float*)d_in[5];
    const float* bn_edge_g = (const float*)d_in[6];
    const float* bn_edge_b = (const float*)d_in[7];
    const float* nn1_w1 = (const float*)d_in[8];
    const float* nn1_b1 = (const float*)d_in[9];
    const float* nn1_w2 = (const float*)d_in[10];
    const float* nn1_b2 = (const float*)d_in[11];
    const float* nn2_w1 = (const float*)d_in[12];
    const float* nn2_b1 = (const float*)d_in[13];
    const float* nn2_w2 = (const float*)d_in[14];
    const float* nn2_b2 = (const float*)d_in[15];
    const float* l1_root = (const float*)d_in[16];
    const float* l1_bias = (const float*)d_in[17];
    const float* l2_root = (const float*)d_in[18];
    const float* l2_bias = (const float*)d_in[19];
    const float* mlp_w1 = (const float*)d_in[20];
    const float* mlp_b1 = (const float*)d_in[21];
    const float* mlp_w2 = (const float*)d_in[22];
    const float* mlp_b2 = (const float*)d_in[23];
    const float* mlp_w3 = (const float*)d_in[24];
    const float* mlp_b3 = (const float*)d_in[25];
    const float* mlp_w4 = (const float*)d_in[26];
    const float* mlp_b4 = (const float*)d_in[27];
    const float* mlp_w5 = (const float*)d_in[28];
    const float* mlp_b5 = (const float*)d_in[29];
    float* out = (float*)d_out;

    bn_stats_edge<<<10, 256>>>(e);
    bn_stats_node<<<16, 256>>>(x);
    prep_w1<<<32, 256>>>(nn1_w2);
    prep_w2<<<256, 256>>>(nn2_w2);
    k1_edge<<<(NE + 255) / 256, 256>>>(e, bn_edge_g, bn_edge_b, nn1_w1, nn1_b1, nn2_w1, nn2_b1);
    k2_node<<<(NN + 255) / 256, 256>>>(x, bn_node_g, bn_node_b, l1_root, l1_bias);
    k3_conv1<<<(NE + 63) / 64, 256>>>(ei, nn1_b2);
    k4_node<<<(NN * 64 + 255) / 256, 256>>>(l2_root, l2_bias);
    k5_conv2<<<NE / 32, 256>>>(ei, nn2_b2);
    k6a_mlp1<<<NE / 16, 256>>>(ei, mlp_w1, mlp_b1);
    k6b_mlp<<<NE / 32, 256>>>(mlp_w2, mlp_b2, mlp_w3, mlp_b3,
                              mlp_w4, mlp_b4, mlp_w5, mlp_b5, out);
}

// round 4
// speedup vs baseline: 1.0851x; 1.0851x over previous
#include <cuda_runtime.h>
#include <cuda_bf16.h>

#define NN 20000
#define NE 100000

typedef unsigned long long ull;

__device__ float g_ebn[NE * 10];
__device__ float g_h1[NE * 16];
__device__ float g_h2[NE * 32];
__device__ float g_xbn[NN * 16];
__device__ float g_x1[NN * 32];
__device__ float g_x2[NN * 64];
__device__ float g_m1[NE * 64];            // edge-MLP layer1 activations
__device__ float g_wT1[2 * 16 * 32 * 8];   // conv1 weights [ic2][j16][o32][il8]
__device__ float g_wT2[8 * 32 * 64 * 4];   // conv2 weights [ic8][j32][o64][il4]
__device__ float g_emean[10], g_ers[10];
__device__ float g_xmean[16], g_xrs[16];

__device__ __forceinline__ float lrelu(float v) { return v > 0.f ? v : 0.1f * v; }

// ---- packed f32x2 helpers (sm_103a FFMA2) -----------------------------------
__device__ __forceinline__ ull bcast2(float v) {
    ull r;
    unsigned u = __float_as_uint(v);
    asm("mov.b64 %0, {%1, %2};" : "=l"(r) : "r"(u), "r"(u));
    return r;
}
__device__ __forceinline__ ull fma2(ull a, ull b, ull c) {
    ull d;
    asm("fma.rn.f32x2 %0, %1, %2, %3;" : "=l"(d) : "l"(a), "l"(b), "l"(c));
    return d;
}
__device__ __forceinline__ float2 unpk2(ull v) {
    unsigned lo, hi;
    asm("mov.b64 {%0, %1}, %2;" : "=r"(lo), "=r"(hi) : "l"(v));
    return make_float2(__uint_as_float(lo), __uint_as_float(hi));
}

// ---------------- BatchNorm statistics (biased var, eps=1e-5) ----------------
__device__ void bn_stats_impl(const float* __restrict__ v, int rows, int cols, int c,
                              float* mean_out, float* rs_out) {
    int tid = threadIdx.x;
    double s = 0.0, ss = 0.0;
    for (int r = tid; r < rows; r += blockDim.x) {
        float f = v[(size_t)r * cols + c];
        s += (double)f;
        ss += (double)f * (double)f;
    }
    __shared__ double sh[256];
    sh[tid] = s; __syncthreads();
    for (int off = 128; off > 0; off >>= 1) { if (tid < off) sh[tid] += sh[tid + off]; __syncthreads(); }
    double stot = sh[0]; __syncthreads();
    sh[tid] = ss; __syncthreads();
    for (int off = 128; off > 0; off >>= 1) { if (tid < off) sh[tid] += sh[tid + off]; __syncthreads(); }
    if (tid == 0) {
        double m = stot / rows;
        double var = sh[0] / rows - m * m;
        mean_out[c] = (float)m;
        rs_out[c] = (float)(1.0 / sqrt(var + 1e-5));
    }
}

__global__ void bn_stats_all(const float* __restrict__ e, const float* __restrict__ x) {
    if (blockIdx.x < 10) bn_stats_impl(e, NE, 10, blockIdx.x, g_emean, g_ers);
    else                 bn_stats_impl(x, NN, 16, blockIdx.x - 10, g_xmean, g_xrs);
}

// ---------------- weight transposes (merged) ---------------------------------
__global__ void prep_w(const float* __restrict__ w1g, const float* __restrict__ w2g) {
    int b = blockIdx.x;
    if (b < 32) {  // nn1_w2 [16,512] -> [ic2][j16][o32][il8]
        int idx = b * 256 + threadIdx.x;
        int il = idx & 7, o = (idx >> 3) & 31, j = (idx >> 8) & 15, ic = (idx >> 12) & 1;
        g_wT1[((ic * 16 + j) * 32 + o) * 8 + il] = w1g[j * 512 + (ic * 8 + il) * 32 + o];
    } else {       // nn2_w2 [32,2048] -> [ic8][j32][o64][il4]
        int idx = (b - 32) * 256 + threadIdx.x;
        int il = idx & 3, o = (idx >> 2) & 63, j = (idx >> 8) & 31, ic = (idx >> 13) & 7;
        g_wT2[((ic * 32 + j) * 64 + o) * 4 + il] = w2g[j * 2048 + (ic * 4 + il) * 64 + o];
    }
}

// ---------------- K1: edge BN + h1 + h2 --------------------------------------
__global__ void k1_edge(const float* __restrict__ e,
                        const float* __restrict__ eg, const float* __restrict__ eb,
                        const float* __restrict__ w1, const float* __restrict__ b1,
                        const float* __restrict__ w2, const float* __restrict__ b2) {
    __shared__ float sw1[160], sw2[320], sb1[16], sb2[32], sg[10], sb[10], sm[10], srs[10];
    int tid = threadIdx.x;
    for (int i = tid; i < 160; i += 256) sw1[i] = w1[i];
    for (int i = tid; i < 320; i += 256) sw2[i] = w2[i];
    if (tid < 16) sb1[tid] = b1[tid];
    if (tid < 32) sb2[tid] = b2[tid];
    if (tid < 10) { sg[tid] = eg[tid]; sb[tid] = eb[tid]; sm[tid] = g_emean[tid]; srs[tid] = g_ers[tid]; }
    __syncthreads();
    int eid = blockIdx.x * 256 + tid;
    if (eid >= NE) return;
    float ev[10];
#pragma unroll
    for (int c = 0; c < 10; c++) {
        float f = (e[eid * 10 + c] - sm[c]) * srs[c] * sg[c] + sb[c];
        ev[c] = f;
        g_ebn[eid * 10 + c] = f;
    }
#pragma unroll
    for (int o = 0; o < 16; o++) {
        float t = sb1[o];
#pragma unroll
        for (int c = 0; c < 10; c++) t += ev[c] * sw1[c * 16 + o];
        g_h1[eid * 16 + o] = lrelu(t);
    }
#pragma unroll
    for (int o = 0; o < 32; o++) {
        float t = sb2[o];
#pragma unroll
        for (int c = 0; c < 10; c++) t += ev[c] * sw2[c * 32 + o];
        g_h2[eid * 32 + o] = lrelu(t);
    }
}

// ---------------- K2: node BN + x1 = xbn @ l1_root + l1_bias -----------------
__global__ void k2_node(const float* __restrict__ x,
                        const float* __restrict__ ng, const float* __restrict__ nb,
                        const float* __restrict__ root, const float* __restrict__ bias) {
    __shared__ float sroot[512], sbias[32], sg[16], sb[16], sm[16], srs[16];
    int tid = threadIdx.x;
    for (int i = tid; i < 512; i += 256) sroot[i] = root[i];
    if (tid < 32) sbias[tid] = bias[tid];
    if (tid < 16) { sg[tid] = ng[tid]; sb[tid] = nb[tid]; sm[tid] = g_xmean[tid]; srs[tid] = g_xrs[tid]; }
    __syncthreads();
    int nid = blockIdx.x * 256 + tid;
    if (nid >= NN) return;
    float xv[16];
#pragma unroll
    for (int i = 0; i < 16; i++) {
        float f = (x[nid * 16 + i] - sm[i]) * srs[i] * sg[i] + sb[i];
        xv[i] = f;
        g_xbn[nid * 16 + i] = f;
    }
#pragma unroll
    for (int o = 0; o < 32; o++) {
        float t = sbias[o];
#pragma unroll
        for (int i = 0; i < 16; i++) t += xv[i] * sroot[i * 32 + o];
        g_x1[nid * 32 + o] = t;
    }
}

// ---------------- K3: NNConv1 message + scatter (FFMA2) ----------------------
__global__ __launch_bounds__(256) void k3_conv1(const int* __restrict__ ei,
                                                const float* __restrict__ b2) {
    __shared__ __align__(16) float swT[8192];     // 2*16*32*8
    __shared__ __align__(16) float h_sh[16 * 68];
    __shared__ __align__(16) float x_sh[64 * 16];
    __shared__ int dst_sh[64];
    int tid = threadIdx.x;
    int e0 = blockIdx.x * 64;
    for (int i = tid; i < 8192; i += 256) swT[i] = g_wT1[i];
    if (tid < 64) {
        int ge = e0 + tid;
        dst_sh[tid] = (ge < NE) ? ei[NE + ge] : 0;
    }
    for (int i = tid; i < 1024; i += 256) {
        int el = i >> 4, j = i & 15;
        int ge = e0 + el;
        h_sh[j * 68 + el] = (ge < NE) ? g_h1[ge * 16 + j] : 0.f;
    }
    for (int i = tid; i < 1024; i += 256) {
        int el = i >> 4, ii = i & 15;
        int ge = e0 + el;
        x_sh[el * 16 + ii] = (ge < NE) ? g_xbn[ei[ge] * 16 + ii] : 0.f;
    }
    __syncthreads();

    int o = tid & 31;
    int w = tid >> 5;
    float acc[8];
#pragma unroll
    for (int eL = 0; eL < 8; eL++) acc[eL] = 0.f;

#pragma unroll
    for (int ic = 0; ic < 2; ic++) {
        ull t2[4][8];
#pragma unroll
        for (int il = 0; il < 8; il++) {
            ull bp = bcast2(b2[(ic * 8 + il) * 32 + o]);
#pragma unroll
            for (int p = 0; p < 4; p++) t2[p][il] = bp;
        }

#pragma unroll 4
        for (int j = 0; j < 16; j++) {
            const ull* hp = (const ull*)&h_sh[j * 68 + w * 8];
            ulonglong2 hA = *(const ulonglong2*)hp;
            ulonglong2 hB = *(const ulonglong2*)(hp + 2);
            ull hv2[4] = {hA.x, hA.y, hB.x, hB.y};
            const float* wp = &swT[((ic * 16 + j) * 32 + o) * 8];
            float4 wa = *(const float4*)wp;
            float4 wb = *(const float4*)(wp + 4);
            ull w2[8] = {bcast2(wa.x), bcast2(wa.y), bcast2(wa.z), bcast2(wa.w),
                         bcast2(wb.x), bcast2(wb.y), bcast2(wb.z), bcast2(wb.w)};
#pragma unroll
            for (int p = 0; p < 4; p++)
#pragma unroll
                for (int il = 0; il < 8; il++) t2[p][il] = fma2(hv2[p], w2[il], t2[p][il]);
        }
#pragma unroll
        for (int p = 0; p < 4; p++)
#pragma unroll
            for (int il = 0; il < 8; il++) {
                float2 v = unpk2(t2[p][il]);
                acc[2 * p]     += x_sh[(w * 8 + 2 * p) * 16 + ic * 8 + il] * lrelu(v.x);
                acc[2 * p + 1] += x_sh[(w * 8 + 2 * p + 1) * 16 + ic * 8 + il] * lrelu(v.y);
            }
    }
#pragma unroll
    for (int eL = 0; eL < 8; eL++) {
        int ge = e0 + w * 8 + eL;
        if (ge < NE) atomicAdd(&g_x1[dst_sh[w * 8 + eL] * 32 + o], acc[eL]);
    }
}

// ---------------- K4: x2 = x1 @ l2_root + l2_bias ----------------------------
__global__ void k4_node(const float* __restrict__ root, const float* __restrict__ bias) {
    __shared__ float sroot[2048], sbias[64];
    int tid = threadIdx.x;
    for (int i = tid; i < 2048; i += 256) sroot[i] = root[i];
    if (tid < 64) sbias[tid] = bias[tid];
    __syncthreads();
    int idx = blockIdx.x * 256 + tid;
    if (idx >= NN * 64) return;
    int n = idx >> 6, o = idx & 63;
    float t = sbias[o];
#pragma unroll
    for (int i = 0; i < 32; i++) t += g_x1[n * 32 + i] * sroot[i * 64 + o];
    g_x2[idx] = t;
}

// ---------------- K5: NNConv2 message + scatter (dominant, FFMA2) ------------
__global__ __launch_bounds__(256) void k5_conv2(const int* __restrict__ ei,
                                                const float* __restrict__ b2) {
    __shared__ __align__(16) float w_sh[8192];   // 32KB chunk: [j][o][il4]
    __shared__ __align__(16) float h_sh[32 * 36];
    __shared__ __align__(16) float x_sh[32 * 32];
    __shared__ int dst_sh[32];
    int tid = threadIdx.x;
    int e0 = blockIdx.x * 32;

    if (tid < 32) dst_sh[tid] = ei[NE + e0 + tid];
    for (int i = tid; i < 1024; i += 256) {
        int el = i >> 5, j = i & 31;
        h_sh[j * 36 + el] = g_h2[(e0 + el) * 32 + j];
    }
    for (int i = tid; i < 1024; i += 256) {
        int el = i >> 5, ii = i & 31;
        x_sh[el * 32 + ii] = g_x1[ei[e0 + el] * 32 + ii];
    }

    int o = tid & 63;
    int g = tid >> 6;
    float acc[8];
#pragma unroll
    for (int eL = 0; eL < 8; eL++) acc[eL] = 0.f;

    for (int ic = 0; ic < 8; ic++) {
        __syncthreads();   // protects h/x initial fill + w_sh reuse
        for (int i = tid; i < 8192; i += 256) w_sh[i] = g_wT2[ic * 8192 + i];
        __syncthreads();

        ull t2[4][4];
#pragma unroll
        for (int il = 0; il < 4; il++) {
            ull bp = bcast2(b2[(ic * 4 + il) * 64 + o]);
#pragma unroll
            for (int p = 0; p < 4; p++) t2[p][il] = bp;
        }

#pragma unroll 4
        for (int j = 0; j < 32; j++) {
            const ull* hp = (const ull*)&h_sh[j * 36 + g * 8];
            ulonglong2 hA = *(const ulonglong2*)hp;
            ulonglong2 hB = *(const ulonglong2*)(hp + 2);
            ull hv2[4] = {hA.x, hA.y, hB.x, hB.y};
            float4 wv = *(const float4*)&w_sh[(j * 64 + o) * 4];
            ull w2[4] = {bcast2(wv.x), bcast2(wv.y), bcast2(wv.z), bcast2(wv.w)};
#pragma unroll
            for (int p = 0; p < 4; p++)
#pragma unroll
                for (int il = 0; il < 4; il++) t2[p][il] = fma2(hv2[p], w2[il], t2[p][il]);
        }
#pragma unroll
        for (int p = 0; p < 4; p++)
#pragma unroll
            for (int il = 0; il < 4; il++) {
                float2 v = unpk2(t2[p][il]);
                acc[2 * p]     += x_sh[(g * 8 + 2 * p) * 32 + ic * 4 + il] * lrelu(v.x);
                acc[2 * p + 1] += x_sh[(g * 8 + 2 * p + 1) * 32 + ic * 4 + il] * lrelu(v.y);
            }
    }
#pragma unroll
    for (int eL = 0; eL < 8; eL++)
        atomicAdd(&g_x2[dst_sh[g * 8 + eL] * 64 + o], acc[eL]);
}

// ---------------- K6a: edge MLP layer1 (138 -> 64, FFMA2) --------------------
__global__ __launch_bounds__(256) void k6a_mlp1(const int* __restrict__ ei,
                                                const float* __restrict__ w1,
                                                const float* __restrict__ b1) {
    __shared__ float sw1[138 * 64];               // 34.5KB
    __shared__ float sb1[64];
    __shared__ __align__(16) float in_sh[138 * 20]; // [k][e] pad 20
    int tid = threadIdx.x;
    int e0 = blockIdx.x * 16;

    for (int i = tid; i < 8832; i += 256) sw1[i] = w1[i];
    if (tid < 64) sb1[tid] = b1[tid];
    for (int i = tid; i < 138 * 16; i += 256) {
        int e = i & 15, k = i >> 4;
        float v;
        if (k < 64)       v = g_x2[ei[e0 + e] * 64 + k];
        else if (k < 128) v = g_x2[ei[NE + e0 + e] * 64 + (k - 64)];
        else              v = g_ebn[(e0 + e) * 10 + (k - 128)];
        in_sh[k * 20 + e] = v;
    }
    __syncthreads();

    int o = tid & 63, g = tid >> 6;
    ull a0 = bcast2(sb1[o]);
    ull a1 = a0;
#pragma unroll 2
    for (int k = 0; k < 138; k++) {
        ull wb = bcast2(sw1[k * 64 + o]);
        ulonglong2 h = *(const ulonglong2*)&in_sh[k * 20 + g * 4];
        a0 = fma2(h.x, wb, a0);
        a1 = fma2(h.y, wb, a1);
    }
    float2 v0 = unpk2(a0), v1 = unpk2(a1);
    g_m1[(e0 + g * 4 + 0) * 64 + o] = lrelu(v0.x);
    g_m1[(e0 + g * 4 + 1) * 64 + o] = lrelu(v0.y);
    g_m1[(e0 + g * 4 + 2) * 64 + o] = lrelu(v1.x);
    g_m1[(e0 + g * 4 + 3) * 64 + o] = lrelu(v1.y);
}

// ---------------- K6b: edge MLP layers 2-5 -----------------------------------
__global__ __launch_bounds__(256) void k6b_mlp(
    const float* __restrict__ w2, const float* __restrict__ b2,
    const float* __restrict__ w3, const float* __restrict__ b3,
    const float* __restrict__ w4, const float* __restrict__ b4,
    const float* __restrict__ w5, const float* __restrict__ b5,
    float* __restrict__ out) {
    __shared__ float sw2[2048], sw3[512], sw4[128], sw5[16];
    __shared__ float sb2[32], sb3[16], sb4[8], sb5[2];
    __shared__ __align__(16) float h1_sh[64 * 36];  // [k][e] pad 36
    __shared__ __align__(16) float h2_sh[32 * 36];
    int tid = threadIdx.x;
    int e0 = blockIdx.x * 32;

    for (int i = tid; i < 2048; i += 256) sw2[i] = w2[i];
    for (int i = tid; i < 512; i += 256) sw3[i] = w3[i];
    if (tid < 128) sw4[tid] = w4[tid];
    if (tid < 16) sw5[tid] = w5[tid];
    if (tid < 32) sb2[tid] = b2[tid];
    if (tid < 16) sb3[tid] = b3[tid];
    if (tid < 8) sb4[tid] = b4[tid];
    if (tid < 2) sb5[tid] = b5[tid];
    for (int i = tid; i < 2048; i += 256) {
        int e = i & 31, k = i >> 5;
        h1_sh[k * 36 + e] = g_m1[(e0 + e) * 64 + k];
    }
    __syncthreads();

    // layer 2: 64 -> 32, 8 groups x 4 edges (FFMA2)
    {
        int o = tid & 31, g = tid >> 5;
        ull a0 = bcast2(sb2[o]);
        ull a1 = a0;
#pragma unroll 4
        for (int k = 0; k < 64; k++) {
            ull wb = bcast2(sw2[k * 32 + o]);
            ulonglong2 h = *(const ulonglong2*)&h1_sh[k * 36 + g * 4];
            a0 = fma2(h.x, wb, a0);
            a1 = fma2(h.y, wb, a1);
        }
        float2 v0 = unpk2(a0), v1 = unpk2(a1);
        h2_sh[o * 36 + g * 4 + 0] = lrelu(v0.x);
        h2_sh[o * 36 + g * 4 + 1] = lrelu(v0.y);
        h2_sh[o * 36 + g * 4 + 2] = lrelu(v1.x);
        h2_sh[o * 36 + g * 4 + 3] = lrelu(v1.y);
    }
    __syncthreads();

    // layers 3-5: one thread per edge
    if (tid < 32) {
        int e = tid, ge = e0 + e;
        float h2r[32];
#pragma unroll
        for (int k = 0; k < 32; k++) h2r[k] = h2_sh[k * 36 + e];
        float h3[16];
#pragma unroll
        for (int o = 0; o < 16; o++) {
            float a = sb3[o];
#pragma unroll
            for (int k = 0; k < 32; k++) a += h2r[k] * sw3[k * 16 + o];
            h3[o] = lrelu(a);
        }
        float h4[8];
#pragma unroll
        for (int o = 0; o < 8; o++) {
            float a = sb4[o];
#pragma unroll
            for (int k = 0; k < 16; k++) a += h3[k] * sw4[k * 8 + o];
            h4[o] = lrelu(a);
        }
#pragma unroll
        for (int o = 0; o < 2; o++) {
            float a = sb5[o];
#pragma unroll
            for (int k = 0; k < 8; k++) a += h4[k] * sw5[k * 2 + o];
            out[(size_t)ge * 2 + o] = a;
        }
    }
}

// ---------------- launch -----------------------------------------------------
extern "C" void kernel_launch(void* const* d_in, const int* in_sizes, int n_in,
                              void* d_out, int out_size) {
    const float* x = (const float*)d_in[0];
    const float* e = (const float*)d_in[1];
    const int* ei = (const int*)d_in[2];     // edge_index: int32
    // d_in[3] xbatch unused
    const float* bn_node_g = (const float*)d_in[4];
    const float* bn_node_b = (const float*)d_in[5];
    const float* bn_edge_g = (const float*)d_in[6];
    const float* bn_edge_b = (const float*)d_in[7];
    const float* nn1_w1 = (const float*)d_in[8];
    const float* nn1_b1 = (const float*)d_in[9];
    const float* nn1_w2 = (const float*)d_in[10];
    const float* nn1_b2 = (const float*)d_in[11];
    const float* nn2_w1 = (const float*)d_in[12];
    const float* nn2_b1 = (const float*)d_in[13];
    const float* nn2_w2 = (const float*)d_in[14];
    const float* nn2_b2 = (const float*)d_in[15];
    const float* l1_root = (const float*)d_in[16];
    const float* l1_bias = (const float*)d_in[17];
    const float* l2_root = (const float*)d_in[18];
    const float* l2_bias = (const float*)d_in[19];
    const float* mlp_w1 = (const float*)d_in[20];
    const float* mlp_b1 = (const float*)d_in[21];
    const float* mlp_w2 = (const float*)d_in[22];
    const float* mlp_b2 = (const float*)d_in[23];
    const float* mlp_w3 = (const float*)d_in[24];
    const float* mlp_b3 = (const float*)d_in[25];
    const float* mlp_w4 = (const float*)d_in[26];
    const float* mlp_b4 = (const float*)d_in[27];
    const float* mlp_w5 = (const float*)d_in[28];
    const float* mlp_b5 = (const float*)d_in[29];
    float* out = (float*)d_out;

    bn_stats_all<<<26, 256>>>(e, x);
    prep_w<<<288, 256>>>(nn1_w2, nn2_w2);
    k1_edge<<<(NE + 255) / 256, 256>>>(e, bn_edge_g, bn_edge_b, nn1_w1, nn1_b1, nn2_w1, nn2_b1);
    k2_node<<<(NN + 255) / 256, 256>>>(x, bn_node_g, bn_node_b, l1_root, l1_bias);
    k3_conv1<<<(NE + 63) / 64, 256>>>(ei, nn1_b2);
    k4_node<<<(NN * 64 + 255) / 256, 256>>>(l2_root, l2_bias);
    k5_conv2<<<NE / 32, 256>>>(ei, nn2_b2);
    k6a_mlp1<<<NE / 16, 256>>>(ei, mlp_w1, mlp_b1);
    k6b_mlp<<<NE / 32, 256>>>(mlp_w2, mlp_b2, mlp_w3, mlp_b3,
                              mlp_w4, mlp_b4, mlp_w5, mlp_b5, out);
}